// round 2
// baseline (speedup 1.0000x reference)
#include <cuda_runtime.h>

#define N_NODES   262144
#define N_EDGES   4194304
#define NUM_GRAPHS 1024

// ---------------- scratch (device globals; no allocations allowed) ----------
__device__ float4 g_agg[N_NODES * 4];      // agg: (N_NODES, 16) f32
__device__ float4 g_cnt4[N_NODES / 4];     // cnt: (N_NODES,) f32
__device__ float4 g_pooled[NUM_GRAPHS * 8]; // pooled: (NUM_GRAPHS, 2, 16) f32

// ---------------- vector reduction helpers (sm_90+ red.v4) ------------------
__device__ __forceinline__ void red_add_v4(float4* addr, float a, float b, float c, float d) {
    asm volatile("red.global.add.v4.f32 [%0], {%1,%2,%3,%4};"
                 :: "l"(addr), "f"(a), "f"(b), "f"(c), "f"(d) : "memory");
}
__device__ __forceinline__ void red_add_f(float* addr, float v) {
    asm volatile("red.global.add.f32 [%0], %1;" :: "l"(addr), "f"(v) : "memory");
}

// ---------------- kernel 0: zero scratch ------------------------------------
// total float4 slots: agg 1048576 + cnt 65536 + pooled 8192 = 1122304
__global__ void zero_kernel() {
    int i = blockIdx.x * blockDim.x + threadIdx.x;
    const float4 z = make_float4(0.f, 0.f, 0.f, 0.f);
    if (i < N_NODES * 4) {
        g_agg[i] = z;
    } else if (i < N_NODES * 4 + N_NODES / 4) {
        g_cnt4[i - N_NODES * 4] = z;
    } else if (i < N_NODES * 4 + N_NODES / 4 + NUM_GRAPHS * 8) {
        g_pooled[i - N_NODES * 4 - N_NODES / 4] = z;
    }
}

// ---------------- kernel 1: edge MLP + scatter -------------------------------
__global__ void __launch_bounds__(256) edge_kernel(
    const float* __restrict__ x, const float* __restrict__ pos,
    const int* __restrict__ ei,
    const float* __restrict__ w1, const float* __restrict__ b1,
    const float* __restrict__ w2, const float* __restrict__ b2)
{
    __shared__ float sw1[9 * 16];
    __shared__ float sb1[16];
    __shared__ float sw2[16 * 16];
    __shared__ float sb2[16];

    int t = threadIdx.x;
    if (t < 144) sw1[t] = w1[t];
    if (t < 256) sw2[t] = w2[t];
    if (t < 16)  { sb1[t] = b1[t]; sb2[t] = b2[t]; }
    __syncthreads();

    int e = blockIdx.x * blockDim.x + t;
    if (e >= N_EDGES) return;

    int s = ei[e];
    int d = ei[N_EDGES + e];

    // rel_pos + dist
    float psx = pos[3 * s + 0], psy = pos[3 * s + 1], psz = pos[3 * s + 2];
    float pdx = pos[3 * d + 0], pdy = pos[3 * d + 1], pdz = pos[3 * d + 2];
    float rx = psx - pdx, ry = psy - pdy, rz = psz - pdz;
    float dist = sqrtf(rx * rx + ry * ry + rz * rz);

    float4 xd = reinterpret_cast<const float4*>(x)[d];
    float4 xs = reinterpret_cast<const float4*>(x)[s];

    float feat[9];
    feat[0] = xd.x; feat[1] = xd.y; feat[2] = xd.z; feat[3] = xd.w;
    feat[4] = xs.x; feat[5] = xs.y; feat[6] = xs.z; feat[7] = xs.w;
    feat[8] = dist;

    float hid[16];
#pragma unroll
    for (int j = 0; j < 16; j++) hid[j] = sb1[j];
#pragma unroll
    for (int i = 0; i < 9; i++) {
        float f = feat[i];
#pragma unroll
        for (int j = 0; j < 16; j++) hid[j] = fmaf(f, sw1[i * 16 + j], hid[j]);
    }
    // SiLU
#pragma unroll
    for (int j = 0; j < 16; j++) {
        float u = hid[j];
        hid[j] = u * __frcp_rn(1.f + __expf(-u));
    }

    float msg[16];
#pragma unroll
    for (int j = 0; j < 16; j++) msg[j] = sb2[j];
#pragma unroll
    for (int i = 0; i < 16; i++) {
        float h = hid[i];
#pragma unroll
        for (int j = 0; j < 16; j++) msg[j] = fmaf(h, sw2[i * 16 + j], msg[j]);
    }

    float4* aggp = &g_agg[d * 4];
    red_add_v4(aggp + 0, msg[0],  msg[1],  msg[2],  msg[3]);
    red_add_v4(aggp + 1, msg[4],  msg[5],  msg[6],  msg[7]);
    red_add_v4(aggp + 2, msg[8],  msg[9],  msg[10], msg[11]);
    red_add_v4(aggp + 3, msg[12], msg[13], msg[14], msg[15]);
    red_add_f(&reinterpret_cast<float*>(g_cnt4)[d], 1.0f);
}

// ---------------- kernel 2: node mean/relu + softmax pooling ----------------
__global__ void __launch_bounds__(256) node_kernel(
    const int* __restrict__ batch,
    const float* __restrict__ pool_w, const float* __restrict__ pool_b,
    float* __restrict__ out_s)
{
    int n = blockIdx.x * blockDim.x + threadIdx.x;
    if (n >= N_NODES) return;

    float4 a0 = g_agg[n * 4 + 0];
    float4 a1 = g_agg[n * 4 + 1];
    float4 a2 = g_agg[n * 4 + 2];
    float4 a3 = g_agg[n * 4 + 3];
    float cnt = fmaxf(reinterpret_cast<const float*>(g_cnt4)[n], 1.0f);
    float inv = __frcp_rn(cnt);

    float h[16];
    h[0]  = fmaxf(a0.x * inv, 0.f); h[1]  = fmaxf(a0.y * inv, 0.f);
    h[2]  = fmaxf(a0.z * inv, 0.f); h[3]  = fmaxf(a0.w * inv, 0.f);
    h[4]  = fmaxf(a1.x * inv, 0.f); h[5]  = fmaxf(a1.y * inv, 0.f);
    h[6]  = fmaxf(a1.z * inv, 0.f); h[7]  = fmaxf(a1.w * inv, 0.f);
    h[8]  = fmaxf(a2.x * inv, 0.f); h[9]  = fmaxf(a2.y * inv, 0.f);
    h[10] = fmaxf(a2.z * inv, 0.f); h[11] = fmaxf(a2.w * inv, 0.f);
    h[12] = fmaxf(a3.x * inv, 0.f); h[13] = fmaxf(a3.y * inv, 0.f);
    h[14] = fmaxf(a3.z * inv, 0.f); h[15] = fmaxf(a3.w * inv, 0.f);

    float l0 = pool_b[0], l1 = pool_b[1];
#pragma unroll
    for (int i = 0; i < 16; i++) {
        l0 = fmaf(h[i], pool_w[i * 2 + 0], l0);
        l1 = fmaf(h[i], pool_w[i * 2 + 1], l1);
    }
    float m  = fmaxf(l0, l1);
    float e0 = __expf(l0 - m), e1 = __expf(l1 - m);
    float is = __frcp_rn(e0 + e1);
    float s0 = e0 * is, s1 = e1 * is;

    out_s[2 * n + 0] = s0;
    out_s[2 * n + 1] = s1;

    int g = batch[n];
    float4* pp = &g_pooled[g * 8];
    red_add_v4(pp + 0, s0 * h[0],  s0 * h[1],  s0 * h[2],  s0 * h[3]);
    red_add_v4(pp + 1, s0 * h[4],  s0 * h[5],  s0 * h[6],  s0 * h[7]);
    red_add_v4(pp + 2, s0 * h[8],  s0 * h[9],  s0 * h[10], s0 * h[11]);
    red_add_v4(pp + 3, s0 * h[12], s0 * h[13], s0 * h[14], s0 * h[15]);
    red_add_v4(pp + 4, s1 * h[0],  s1 * h[1],  s1 * h[2],  s1 * h[3]);
    red_add_v4(pp + 5, s1 * h[4],  s1 * h[5],  s1 * h[6],  s1 * h[7]);
    red_add_v4(pp + 6, s1 * h[8],  s1 * h[9],  s1 * h[10], s1 * h[11]);
    red_add_v4(pp + 7, s1 * h[12], s1 * h[13], s1 * h[14], s1 * h[15]);
}

// ---------------- kernel 3: per-graph head ----------------------------------
__global__ void graph_kernel(
    const float* __restrict__ toz_w, const float* __restrict__ toz_b,
    const float* __restrict__ vp_w1, const float* __restrict__ vp_b1,
    const float* __restrict__ vp_w2, const float* __restrict__ vp_b2,
    const float* __restrict__ bridge_w, const float* __restrict__ bridge_b,
    float* __restrict__ out_recon,   // (1024, 8, 4)
    float* __restrict__ out_z,       // (1024, 2, 4)
    float* __restrict__ out_forces,  // (1024, 2, 2)
    float* __restrict__ out_V)       // (1024, 1)
{
    int g = blockIdx.x * blockDim.x + threadIdx.x;
    if (g >= NUM_GRAPHS) return;

    float p[32];
    const float* pp = reinterpret_cast<const float*>(&g_pooled[g * 8]);
#pragma unroll
    for (int i = 0; i < 32; i++) p[i] = pp[i];

    // z = pooled @ toz_w + toz_b   (2x16 @ 16x4)
    float z[8];
#pragma unroll
    for (int k = 0; k < 2; k++) {
#pragma unroll
        for (int c = 0; c < 4; c++) {
            float acc = toz_b[c];
#pragma unroll
            for (int i = 0; i < 16; i++)
                acc = fmaf(p[k * 16 + i], toz_w[i * 4 + c], acc);
            z[k * 4 + c] = acc;
        }
    }
#pragma unroll
    for (int i = 0; i < 8; i++) out_z[g * 8 + i] = z[i];

    // recon = zflat(8) @ bridge_w(8,32) + b
#pragma unroll
    for (int j = 0; j < 32; j++) {
        float acc = bridge_b[j];
#pragma unroll
        for (int i = 0; i < 8; i++)
            acc = fmaf(z[i], bridge_w[i * 32 + j], acc);
        out_recon[g * 32 + j] = acc;
    }

    // potential + analytic forces (K=2 -> single pair)
    float dx = z[0] - z[4];
    float dy = z[1] - z[5];
    float dist = sqrtf(dx * dx + dy * dy + 1e-6f);

    float V = vp_b2[0];
    float fp = 0.f;
#pragma unroll
    for (int j = 0; j < 32; j++) {
        float w1 = vp_w1[j];
        float w2 = vp_w2[j];
        float t = fmaf(dist, w1, vp_b1[j]);
        // stable softplus
        float sp = fmaxf(t, 0.f) + log1pf(expf(-fabsf(t)));
        V = fmaf(sp, w2, V);
        float sig = 1.f / (1.f + expf(-t));
        fp = fmaf(sig * w1, w2, fp);
    }
    float c = fp / dist;
    out_forces[g * 4 + 0] = -c * dx;
    out_forces[g * 4 + 1] = -c * dy;
    out_forces[g * 4 + 2] =  c * dx;
    out_forces[g * 4 + 3] =  c * dy;
    out_V[g] = V;
}

// ---------------- launch -----------------------------------------------------
extern "C" void kernel_launch(void* const* d_in, const int* in_sizes, int n_in,
                              void* d_out, int out_size)
{
    const float* x        = (const float*)d_in[0];
    const float* pos      = (const float*)d_in[1];
    const int*   ei       = (const int*)  d_in[2];
    const int*   batch    = (const int*)  d_in[3];
    const float* enc_w1   = (const float*)d_in[4];
    const float* enc_b1   = (const float*)d_in[5];
    const float* enc_w2   = (const float*)d_in[6];
    const float* enc_b2   = (const float*)d_in[7];
    const float* pool_w   = (const float*)d_in[8];
    const float* pool_b   = (const float*)d_in[9];
    const float* toz_w    = (const float*)d_in[10];
    const float* toz_b    = (const float*)d_in[11];
    const float* vp_w1    = (const float*)d_in[12];
    const float* vp_b1    = (const float*)d_in[13];
    const float* vp_w2    = (const float*)d_in[14];
    const float* vp_b2    = (const float*)d_in[15];
    const float* bridge_w = (const float*)d_in[16];
    const float* bridge_b = (const float*)d_in[17];

    float* out = (float*)d_out;
    // output layout (flattened tuple order):
    float* out_recon  = out;                 // 1024*8*4 = 32768
    float* out_z      = out + 32768;         // 1024*2*4 =  8192
    float* out_s      = out + 40960;         // 262144*2 = 524288
    float* out_forces = out + 565248;        // 1024*2*2 =  4096
    float* out_V      = out + 569344;        // 1024     =  1024

    const int ZERO_SLOTS = N_NODES * 4 + N_NODES / 4 + NUM_GRAPHS * 8;
    zero_kernel<<<(ZERO_SLOTS + 255) / 256, 256>>>();

    edge_kernel<<<N_EDGES / 256, 256>>>(x, pos, ei, enc_w1, enc_b1, enc_w2, enc_b2);

    node_kernel<<<N_NODES / 256, 256>>>(batch, pool_w, pool_b, out_s);

    graph_kernel<<<4, 256>>>(toz_w, toz_b, vp_w1, vp_b1, vp_w2, vp_b2,
                             bridge_w, bridge_b,
                             out_recon, out_z, out_forces, out_V);
}